// round 1
// baseline (speedup 1.0000x reference)
#include <cuda_runtime.h>
#include <cstdint>

#define N_NODES 100000
#define DD 64
#define OUTW 68

// Scratch (no cudaMalloc allowed): neighbor-sum accumulator + degree
__device__ float g_nsum[(size_t)N_NODES * DD];
__device__ float g_deg[N_NODES];

// ---------------------------------------------------------------------------
// Kernel 1: zero the accumulators
// ---------------------------------------------------------------------------
__global__ void zero_kernel() {
    int tot = N_NODES * DD + N_NODES;
    for (int i = blockIdx.x * blockDim.x + threadIdx.x; i < tot;
         i += gridDim.x * blockDim.x) {
        if (i < N_NODES * DD) g_nsum[i] = 0.f;
        else                  g_deg[i - N_NODES * DD] = 0.f;
    }
}

// ---------------------------------------------------------------------------
// Kernel 2: edge scatter. Each work item = (edge, float4-chunk c of 16).
// Handles BOTH directions for that chunk. Vector red.global.add.v4.f32
// (sm_90+) quarters the reduction-op count vs scalar atomicAdd.
// ---------------------------------------------------------------------------
__global__ void edge_kernel(const int* __restrict__ ei,
                            const float4* __restrict__ feat4,
                            int E) {
    int total = E * 16;
    float4* nsum4 = reinterpret_cast<float4*>(g_nsum);
    for (int idx = blockIdx.x * blockDim.x + threadIdx.x; idx < total;
         idx += gridDim.x * blockDim.x) {
        int e = idx >> 4;
        int c = idx & 15;
        int s = ei[e];
        int d = ei[E + e];
        float4 fs = feat4[(size_t)s * 16 + c];
        float4 fd = feat4[(size_t)d * 16 + c];
        float4* ps = nsum4 + (size_t)s * 16 + c;
        float4* pd = nsum4 + (size_t)d * 16 + c;
        asm volatile("red.global.add.v4.f32 [%0], {%1,%2,%3,%4};" ::
                     "l"(ps), "f"(fd.x), "f"(fd.y), "f"(fd.z), "f"(fd.w)
                     : "memory");
        asm volatile("red.global.add.v4.f32 [%0], {%1,%2,%3,%4};" ::
                     "l"(pd), "f"(fs.x), "f"(fs.y), "f"(fs.z), "f"(fs.w)
                     : "memory");
        if (c == 0) {
            atomicAdd(&g_deg[s], 1.f);
            atomicAdd(&g_deg[d], 1.f);
        }
    }
}

// ---------------------------------------------------------------------------
// Kernel 3: per-node MLP. Weights staged in SMEM; one warp processes 4 nodes
// at a time so every weight LDS feeds 4x the FFMAs (crossbar relief).
// ---------------------------------------------------------------------------
#define WARPS 16
#define THREADS (WARPS * 32)
#define NPW 4   // nodes per warp

// SMEM layout (floats)
#define OFF_W1   0          // 128*128
#define OFF_B1   16384      // 128
#define OFF_W2   16512      // 128*64
#define OFF_B2   24704      // 64
#define OFF_W3   24768      // 64*67
#define OFF_B3   29056      // 67 (pad to 68)
#define OFF_P1   29124      // 64*32
#define OFF_PB1  31172      // 32
#define OFF_P2   31204      // 32
#define OFF_PB2  31236      // 1
#define OFF_SCR  31248      // per-warp scratch: NPW*256 floats each
#define SMEM_FLOATS (OFF_SCR + WARPS * NPW * 256)

__global__ void __launch_bounds__(THREADS, 1)
mlp_kernel(const float* __restrict__ nf,
           const float* __restrict__ ops,
           const float* __restrict__ W1, const float* __restrict__ b1,
           const float* __restrict__ W2, const float* __restrict__ b2,
           const float* __restrict__ W3, const float* __restrict__ b3,
           const float* __restrict__ P1, const float* __restrict__ pb1,
           const float* __restrict__ P2, const float* __restrict__ pb2,
           float* __restrict__ out) {
    extern __shared__ float sm[];
    int tid = threadIdx.x;

    // ---- stage weights ----
    for (int i = tid; i < 16384; i += THREADS) sm[OFF_W1 + i] = W1[i];
    for (int i = tid; i < 128;   i += THREADS) sm[OFF_B1 + i] = b1[i];
    for (int i = tid; i < 8192;  i += THREADS) sm[OFF_W2 + i] = W2[i];
    for (int i = tid; i < 64;    i += THREADS) sm[OFF_B2 + i] = b2[i];
    for (int i = tid; i < 4288;  i += THREADS) sm[OFF_W3 + i] = W3[i];
    for (int i = tid; i < 67;    i += THREADS) sm[OFF_B3 + i] = b3[i];
    for (int i = tid; i < 2048;  i += THREADS) sm[OFF_P1 + i] = P1[i];
    for (int i = tid; i < 32;    i += THREADS) sm[OFF_PB1 + i] = pb1[i];
    for (int i = tid; i < 32;    i += THREADS) sm[OFF_P2 + i] = P2[i];
    if (tid == 0) sm[OFF_PB2] = pb2[0];
    __syncthreads();

    int warpId = tid >> 5;
    int lane   = tid & 31;
    float* ctx = sm + OFF_SCR + warpId * (NPW * 256);     // [NPW][128]
    float* hb  = ctx + NPW * 128;                          // [NPW][128]

    const float4* sW1_4 = reinterpret_cast<const float4*>(sm + OFF_W1);
    const float4* sb1_4 = reinterpret_cast<const float4*>(sm + OFF_B1);
    const float2* sW2_2 = reinterpret_cast<const float2*>(sm + OFF_W2);
    const float2* sb2_2 = reinterpret_cast<const float2*>(sm + OFF_B2);

    const int nGroups = (N_NODES + NPW - 1) / NPW;   // 25000
    int g = blockIdx.x * WARPS + warpId;
    if (g >= nGroups) return;
    {
        int n0 = g * NPW;
        float m[NPW];

        // ---- load ctx = [feat | nmean], compute mask ----
        #pragma unroll
        for (int q = 0; q < NPW; q++) {
            int n = n0 + q;
            float dv  = g_deg[n];
            float inv = 1.f / fmaxf(dv, 1.f);
            ctx[q * 128 + lane]      = nf[(size_t)n * 64 + lane];
            ctx[q * 128 + 32 + lane] = nf[(size_t)n * 64 + 32 + lane];
            ctx[q * 128 + 64 + lane] = g_nsum[(size_t)n * 64 + lane] * inv;
            ctx[q * 128 + 96 + lane] = g_nsum[(size_t)n * 64 + 32 + lane] * inv;
            float o0 = ops[n * 4 + 0], o1 = ops[n * 4 + 1];
            float o2 = ops[n * 4 + 2], o3 = ops[n * 4 + 3];
            float mx = fmaxf(fmaxf(o0, o1), fmaxf(o2, o3));
            float e0 = expf(o0 - mx), e1 = expf(o1 - mx);
            float e2 = expf(o2 - mx), e3 = expf(o3 - mx);
            float p0 = e0 / (e0 + e1 + e2 + e3);
            m[q] = (p0 > 0.5f && dv > 0.f) ? 1.f : 0.f;
        }
        __syncwarp();

        // ---- layer 1: 128 -> 128, relu. lane owns outputs 4*lane..+3 ----
        float4 acc[NPW];
        {
            float4 bb = sb1_4[lane];
            #pragma unroll
            for (int q = 0; q < NPW; q++) acc[q] = bb;
        }
        #pragma unroll 4
        for (int i = 0; i < 128; i++) {
            float4 w = sW1_4[i * 32 + lane];
            #pragma unroll
            for (int q = 0; q < NPW; q++) {
                float c = ctx[q * 128 + i];
                acc[q].x += w.x * c; acc[q].y += w.y * c;
                acc[q].z += w.z * c; acc[q].w += w.w * c;
            }
        }
        #pragma unroll
        for (int q = 0; q < NPW; q++) {
            hb[q * 128 + 4 * lane + 0] = fmaxf(acc[q].x, 0.f);
            hb[q * 128 + 4 * lane + 1] = fmaxf(acc[q].y, 0.f);
            hb[q * 128 + 4 * lane + 2] = fmaxf(acc[q].z, 0.f);
            hb[q * 128 + 4 * lane + 3] = fmaxf(acc[q].w, 0.f);
        }
        __syncwarp();

        // ---- layer 2: 128 -> 64, relu. lane owns outputs 2*lane..+1 ----
        float2 a2[NPW];
        {
            float2 bb = sb2_2[lane];
            #pragma unroll
            for (int q = 0; q < NPW; q++) a2[q] = bb;
        }
        #pragma unroll 4
        for (int i = 0; i < 128; i++) {
            float2 w = sW2_2[i * 32 + lane];
            #pragma unroll
            for (int q = 0; q < NPW; q++) {
                float c = hb[q * 128 + i];
                a2[q].x += w.x * c; a2[q].y += w.y * c;
            }
        }
        #pragma unroll
        for (int q = 0; q < NPW; q++) {
            ctx[q * 128 + 2 * lane + 0] = fmaxf(a2[q].x, 0.f);
            ctx[q * 128 + 2 * lane + 1] = fmaxf(a2[q].y, 0.f);
        }
        __syncwarp();

        // ---- layer 3: 64 -> 67. lane owns outputs lane, lane+32, (lane<3: lane+64)
        float ga[NPW], gb2[NPW], gc[NPW];
        {
            float bA = sm[OFF_B3 + lane];
            float bB = sm[OFF_B3 + 32 + lane];
            float bC = (lane < 3) ? sm[OFF_B3 + 64 + lane] : 0.f;
            #pragma unroll
            for (int q = 0; q < NPW; q++) { ga[q] = bA; gb2[q] = bB; gc[q] = bC; }
        }
        #pragma unroll 2
        for (int i = 0; i < 64; i++) {
            float w1 = sm[OFF_W3 + i * 67 + lane];
            float w2 = sm[OFF_W3 + i * 67 + 32 + lane];
            float w3 = (lane < 3) ? sm[OFF_W3 + i * 67 + 64 + lane] : 0.f;
            #pragma unroll
            for (int q = 0; q < NPW; q++) {
                float c = ctx[q * 128 + i];
                ga[q] += c * w1; gb2[q] += c * w2; gc[q] += c * w3;
            }
        }
        #pragma unroll
        for (int q = 0; q < NPW; q++) {
            hb[q * 128 + lane]      = ga[q];
            hb[q * 128 + 32 + lane] = gb2[q];
            if (lane < 3) hb[q * 128 + 64 + lane] = gc[q];
        }
        __syncwarp();

        // ---- head: feats(64) -> 32 relu -> 1 sigmoid ----
        float pa[NPW];
        {
            float bb = sm[OFF_PB1 + lane];
            #pragma unroll
            for (int q = 0; q < NPW; q++) pa[q] = bb;
        }
        #pragma unroll 2
        for (int i = 0; i < 64; i++) {
            float w = sm[OFF_P1 + i * 32 + lane];
            #pragma unroll
            for (int q = 0; q < NPW; q++) pa[q] += hb[q * 128 + 3 + i] * w;
        }
        float prob[NPW];
        float w2s = sm[OFF_P2 + lane];
        float pb2v = sm[OFF_PB2];
        #pragma unroll
        for (int q = 0; q < NPW; q++) {
            float v = fmaxf(pa[q], 0.f) * w2s;
            #pragma unroll
            for (int o = 16; o > 0; o >>= 1)
                v += __shfl_xor_sync(0xffffffffu, v, o);
            prob[q] = 1.f / (1.f + expf(-(v + pb2v)));
        }

        // ---- write out: 68 per node ----
        #pragma unroll
        for (int q = 0; q < NPW; q++) {
            int n = n0 + q;
            float mm = m[q];
            float* o = out + (size_t)n * OUTW;
            o[lane]      = hb[q * 128 + lane] * mm;
            o[32 + lane] = hb[q * 128 + 32 + lane] * mm;
            if (lane < 3) o[64 + lane] = hb[q * 128 + 64 + lane] * mm;
            if (lane == 3) o[67] = prob[q] * mm;
        }
    }
}

// ---------------------------------------------------------------------------
extern "C" void kernel_launch(void* const* d_in, const int* in_sizes, int n_in,
                              void* d_out, int out_size) {
    const float* nf  = (const float*)d_in[0];
    const float* ops = (const float*)d_in[1];
    const int*   ei  = (const int*)d_in[2];
    const float* W1  = (const float*)d_in[3];
    const float* b1  = (const float*)d_in[4];
    const float* W2  = (const float*)d_in[5];
    const float* b2  = (const float*)d_in[6];
    const float* W3  = (const float*)d_in[7];
    const float* b3  = (const float*)d_in[8];
    const float* P1  = (const float*)d_in[9];
    const float* pb1 = (const float*)d_in[10];
    const float* P2  = (const float*)d_in[11];
    const float* pb2 = (const float*)d_in[12];
    float* out = (float*)d_out;

    int E = in_sizes[2] / 2;

    // zero accumulators
    zero_kernel<<<6400, 512>>>();

    // edge scatter
    int totalItems = E * 16;
    int eblocks = (totalItems + 255) / 256;
    edge_kernel<<<eblocks, 256>>>(ei, (const float4*)nf, E);

    // per-node MLP
    static_assert(SMEM_FLOATS * 4 < 227 * 1024, "smem");
    cudaFuncSetAttribute(mlp_kernel,
                         cudaFuncAttributeMaxDynamicSharedMemorySize,
                         SMEM_FLOATS * 4);
    int nGroups = (N_NODES + NPW - 1) / NPW;           // 25000
    int mblocks = (nGroups + WARPS - 1) / WARPS;       // 1563
    mlp_kernel<<<mblocks, THREADS, SMEM_FLOATS * 4>>>(
        nf, ops, W1, b1, W2, b2, W3, b3, P1, pb1, P2, pb2, out);
}

// round 2
// speedup vs baseline: 3.5903x; 3.5903x over previous
#include <cuda_runtime.h>
#include <cstdint>

#define N_NODES 100000
#define OUTW 68

// Scratch (no cudaMalloc allowed)
__device__ float g_nsum[(size_t)N_NODES * 64];
__device__ float g_deg[N_NODES];
__device__ unsigned char g_pmask[N_NODES];
__device__ int g_list[N_NODES];
__device__ int g_cnt;

// ---------------------------------------------------------------------------
// Kernel 1: per-node softmax gate (insert_probs[:,0] > 0.5), zero deg, counter
// ---------------------------------------------------------------------------
__global__ void pmask_kernel(const float* __restrict__ ops) {
    int n = blockIdx.x * blockDim.x + threadIdx.x;
    if (n == 0) g_cnt = 0;
    if (n >= N_NODES) return;
    float o0 = ops[n * 4 + 0], o1 = ops[n * 4 + 1];
    float o2 = ops[n * 4 + 2], o3 = ops[n * 4 + 3];
    float mx = fmaxf(fmaxf(o0, o1), fmaxf(o2, o3));
    float e0 = expf(o0 - mx), e1 = expf(o1 - mx);
    float e2 = expf(o2 - mx), e3 = expf(o3 - mx);
    float p0 = e0 / (e0 + e1 + e2 + e3);
    g_pmask[n] = (p0 > 0.5f) ? 1 : 0;
    g_deg[n] = 0.f;
}

// ---------------------------------------------------------------------------
// Kernel 2: gated edge scatter. One thread per (edge, direction).
// Skips all gather/reduce work unless the TARGET node passes the softmax gate
// (~13% of nodes), cutting L2 traffic ~8x vs ungated. Loads are batched into
// registers (8 float4 at a time) before the reds so the asm memory clobbers
// don't serialize the gathers.
// ---------------------------------------------------------------------------
__global__ void edge_kernel(const int* __restrict__ ei,
                            const float4* __restrict__ feat4,
                            int E) {
    int t = blockIdx.x * blockDim.x + threadIdx.x;
    if (t >= 2 * E) return;
    int e = t >> 1;
    int dir = t & 1;
    int s = __ldg(&ei[e]);
    int d = __ldg(&ei[E + e]);
    int tgt = dir ? d : s;
    int srcn = dir ? s : d;
    if (!g_pmask[tgt]) return;
    atomicAdd(&g_deg[tgt], 1.f);
    const float4* fs = feat4 + (size_t)srcn * 16;
    float4* pd = reinterpret_cast<float4*>(g_nsum) + (size_t)tgt * 16;
    #pragma unroll
    for (int h = 0; h < 2; h++) {
        float4 v[8];
        #pragma unroll
        for (int c = 0; c < 8; c++) v[c] = __ldg(&fs[h * 8 + c]);
        #pragma unroll
        for (int c = 0; c < 8; c++)
            asm volatile("red.global.add.v4.f32 [%0], {%1,%2,%3,%4};" ::
                         "l"(pd + h * 8 + c),
                         "f"(v[c].x), "f"(v[c].y), "f"(v[c].z), "f"(v[c].w)
                         : "memory");
    }
}

// ---------------------------------------------------------------------------
// Kernel 3: compact active nodes (gate && deg>0) into g_list
// ---------------------------------------------------------------------------
__global__ void compact_kernel() {
    int n = blockIdx.x * blockDim.x + threadIdx.x;
    if (n >= N_NODES) return;
    if (g_pmask[n] && g_deg[n] > 0.f) {
        int p = atomicAdd(&g_cnt, 1);
        g_list[p] = n;
    }
}

// ---------------------------------------------------------------------------
// Kernel 4: MLP over ACTIVE nodes only. Persistent grid (one block/SM) so
// weights are staged into SMEM once per SM. One warp = 4 nodes.
// Mask is guaranteed 1 for all listed nodes -> no mask math.
// ---------------------------------------------------------------------------
#define WARPS 16
#define THREADS (WARPS * 32)
#define NPW 4

#define OFF_W1   0          // 128*128
#define OFF_B1   16384      // 128
#define OFF_W2   16512      // 128*64
#define OFF_B2   24704      // 64
#define OFF_W3   24768      // 64*67
#define OFF_B3   29056      // 67
#define OFF_P1   29124      // 64*32
#define OFF_PB1  31172      // 32
#define OFF_P2   31204      // 32
#define OFF_PB2  31236      // 1
#define OFF_SCR  31248
#define SMEM_FLOATS (OFF_SCR + WARPS * NPW * 256)

__global__ void __launch_bounds__(THREADS, 1)
mlp_kernel(const float* __restrict__ nf,
           const float* __restrict__ W1, const float* __restrict__ b1,
           const float* __restrict__ W2, const float* __restrict__ b2,
           const float* __restrict__ W3, const float* __restrict__ b3,
           const float* __restrict__ P1, const float* __restrict__ pb1,
           const float* __restrict__ P2, const float* __restrict__ pb2,
           float* __restrict__ out) {
    extern __shared__ float sm[];
    int tid = threadIdx.x;

    for (int i = tid; i < 16384; i += THREADS) sm[OFF_W1 + i] = W1[i];
    for (int i = tid; i < 128;   i += THREADS) sm[OFF_B1 + i] = b1[i];
    for (int i = tid; i < 8192;  i += THREADS) sm[OFF_W2 + i] = W2[i];
    for (int i = tid; i < 64;    i += THREADS) sm[OFF_B2 + i] = b2[i];
    for (int i = tid; i < 4288;  i += THREADS) sm[OFF_W3 + i] = W3[i];
    for (int i = tid; i < 67;    i += THREADS) sm[OFF_B3 + i] = b3[i];
    for (int i = tid; i < 2048;  i += THREADS) sm[OFF_P1 + i] = P1[i];
    for (int i = tid; i < 32;    i += THREADS) sm[OFF_PB1 + i] = pb1[i];
    for (int i = tid; i < 32;    i += THREADS) sm[OFF_P2 + i] = P2[i];
    if (tid == 0) sm[OFF_PB2] = pb2[0];
    __syncthreads();

    int warpId = tid >> 5;
    int lane   = tid & 31;
    float* ctx = sm + OFF_SCR + warpId * (NPW * 256);
    float* hb  = ctx + NPW * 128;

    const float4* sW1_4 = reinterpret_cast<const float4*>(sm + OFF_W1);
    const float4* sb1_4 = reinterpret_cast<const float4*>(sm + OFF_B1);
    const float2* sW2_2 = reinterpret_cast<const float2*>(sm + OFF_W2);
    const float2* sb2_2 = reinterpret_cast<const float2*>(sm + OFF_B2);

    const int cnt = g_cnt;
    const int totalWarps = gridDim.x * WARPS;

    for (int g = blockIdx.x * WARPS + warpId; g * NPW < cnt; g += totalWarps) {
        int nn[NPW];
        bool valid[NPW];
        #pragma unroll
        for (int q = 0; q < NPW; q++) {
            int li = g * NPW + q;
            valid[q] = li < cnt;
            nn[q] = g_list[valid[q] ? li : g * NPW];
        }

        // ---- ctx = [feat | nmean] ----
        #pragma unroll
        for (int q = 0; q < NPW; q++) {
            int n = nn[q];
            float inv = 1.f / fmaxf(g_deg[n], 1.f);
            ctx[q * 128 + lane]      = nf[(size_t)n * 64 + lane];
            ctx[q * 128 + 32 + lane] = nf[(size_t)n * 64 + 32 + lane];
            ctx[q * 128 + 64 + lane] = g_nsum[(size_t)n * 64 + lane] * inv;
            ctx[q * 128 + 96 + lane] = g_nsum[(size_t)n * 64 + 32 + lane] * inv;
        }
        __syncwarp();

        // ---- layer 1: 128 -> 128, relu ----
        float4 acc[NPW];
        {
            float4 bb = sb1_4[lane];
            #pragma unroll
            for (int q = 0; q < NPW; q++) acc[q] = bb;
        }
        #pragma unroll 4
        for (int i = 0; i < 128; i++) {
            float4 w = sW1_4[i * 32 + lane];
            #pragma unroll
            for (int q = 0; q < NPW; q++) {
                float c = ctx[q * 128 + i];
                acc[q].x += w.x * c; acc[q].y += w.y * c;
                acc[q].z += w.z * c; acc[q].w += w.w * c;
            }
        }
        #pragma unroll
        for (int q = 0; q < NPW; q++) {
            hb[q * 128 + 4 * lane + 0] = fmaxf(acc[q].x, 0.f);
            hb[q * 128 + 4 * lane + 1] = fmaxf(acc[q].y, 0.f);
            hb[q * 128 + 4 * lane + 2] = fmaxf(acc[q].z, 0.f);
            hb[q * 128 + 4 * lane + 3] = fmaxf(acc[q].w, 0.f);
        }
        __syncwarp();

        // ---- layer 2: 128 -> 64, relu ----
        float2 a2[NPW];
        {
            float2 bb = sb2_2[lane];
            #pragma unroll
            for (int q = 0; q < NPW; q++) a2[q] = bb;
        }
        #pragma unroll 4
        for (int i = 0; i < 128; i++) {
            float2 w = sW2_2[i * 32 + lane];
            #pragma unroll
            for (int q = 0; q < NPW; q++) {
                float c = hb[q * 128 + i];
                a2[q].x += w.x * c; a2[q].y += w.y * c;
            }
        }
        #pragma unroll
        for (int q = 0; q < NPW; q++) {
            ctx[q * 128 + 2 * lane + 0] = fmaxf(a2[q].x, 0.f);
            ctx[q * 128 + 2 * lane + 1] = fmaxf(a2[q].y, 0.f);
        }
        __syncwarp();

        // ---- layer 3: 64 -> 67 ----
        float ga[NPW], gb2[NPW], gc[NPW];
        {
            float bA = sm[OFF_B3 + lane];
            float bB = sm[OFF_B3 + 32 + lane];
            float bC = (lane < 3) ? sm[OFF_B3 + 64 + lane] : 0.f;
            #pragma unroll
            for (int q = 0; q < NPW; q++) { ga[q] = bA; gb2[q] = bB; gc[q] = bC; }
        }
        #pragma unroll 2
        for (int i = 0; i < 64; i++) {
            float w1 = sm[OFF_W3 + i * 67 + lane];
            float w2 = sm[OFF_W3 + i * 67 + 32 + lane];
            float w3 = (lane < 3) ? sm[OFF_W3 + i * 67 + 64 + lane] : 0.f;
            #pragma unroll
            for (int q = 0; q < NPW; q++) {
                float c = ctx[q * 128 + i];
                ga[q] += c * w1; gb2[q] += c * w2; gc[q] += c * w3;
            }
        }
        #pragma unroll
        for (int q = 0; q < NPW; q++) {
            hb[q * 128 + lane]      = ga[q];
            hb[q * 128 + 32 + lane] = gb2[q];
            if (lane < 3) hb[q * 128 + 64 + lane] = gc[q];
        }
        __syncwarp();

        // ---- head: feats(64) -> 32 relu -> 1 sigmoid ----
        float pa[NPW];
        {
            float bb = sm[OFF_PB1 + lane];
            #pragma unroll
            for (int q = 0; q < NPW; q++) pa[q] = bb;
        }
        #pragma unroll 2
        for (int i = 0; i < 64; i++) {
            float w = sm[OFF_P1 + i * 32 + lane];
            #pragma unroll
            for (int q = 0; q < NPW; q++) pa[q] += hb[q * 128 + 3 + i] * w;
        }
        float prob[NPW];
        float w2s = sm[OFF_P2 + lane];
        float pb2v = sm[OFF_PB2];
        #pragma unroll
        for (int q = 0; q < NPW; q++) {
            float v = fmaxf(pa[q], 0.f) * w2s;
            #pragma unroll
            for (int o = 16; o > 0; o >>= 1)
                v += __shfl_xor_sync(0xffffffffu, v, o);
            prob[q] = 1.f / (1.f + expf(-(v + pb2v)));
        }

        // ---- write out (mask == 1 for every listed node) ----
        #pragma unroll
        for (int q = 0; q < NPW; q++) {
            if (!valid[q]) continue;
            float* o = out + (size_t)nn[q] * OUTW;
            o[lane]      = hb[q * 128 + lane];
            o[32 + lane] = hb[q * 128 + 32 + lane];
            if (lane < 3) o[64 + lane] = hb[q * 128 + 64 + lane];
            if (lane == 3) o[67] = prob[q];
        }
        __syncwarp();
    }
}

// ---------------------------------------------------------------------------
extern "C" void kernel_launch(void* const* d_in, const int* in_sizes, int n_in,
                              void* d_out, int out_size) {
    const float* nf  = (const float*)d_in[0];
    const float* ops = (const float*)d_in[1];
    const int*   ei  = (const int*)d_in[2];
    const float* W1  = (const float*)d_in[3];
    const float* b1  = (const float*)d_in[4];
    const float* W2  = (const float*)d_in[5];
    const float* b2  = (const float*)d_in[6];
    const float* W3  = (const float*)d_in[7];
    const float* b3  = (const float*)d_in[8];
    const float* P1  = (const float*)d_in[9];
    const float* pb1 = (const float*)d_in[10];
    const float* P2  = (const float*)d_in[11];
    const float* pb2 = (const float*)d_in[12];
    float* out = (float*)d_out;

    int E = in_sizes[2] / 2;

    // Zero output + neighbor-sum accumulator (memset nodes in the graph)
    void* p_nsum = nullptr;
    cudaGetSymbolAddress(&p_nsum, g_nsum);
    cudaMemsetAsync(d_out, 0, (size_t)out_size * sizeof(float));
    cudaMemsetAsync(p_nsum, 0, sizeof(float) * (size_t)N_NODES * 64);

    // Softmax gate + deg zero + counter reset
    pmask_kernel<<<(N_NODES + 255) / 256, 256>>>(ops);

    // Gated edge scatter: one thread per (edge, direction)
    int tthreads = 2 * E;
    edge_kernel<<<(tthreads + 255) / 256, 256>>>(ei, (const float4*)nf, E);

    // Compact active nodes
    compact_kernel<<<(N_NODES + 255) / 256, 256>>>();

    // Persistent MLP over active nodes
    static_assert(SMEM_FLOATS * 4 < 227 * 1024, "smem");
    cudaFuncSetAttribute(mlp_kernel,
                         cudaFuncAttributeMaxDynamicSharedMemorySize,
                         SMEM_FLOATS * 4);
    mlp_kernel<<<152, THREADS, SMEM_FLOATS * 4>>>(
        nf, W1, b1, W2, b2, W3, b3, P1, pb1, P2, pb2, out);
}

// round 3
// speedup vs baseline: 3.6506x; 1.0168x over previous
#include <cuda_runtime.h>
#include <cstdint>

#define N_NODES 100000
#define OUTW 68

__device__ float g_nsum[(size_t)N_NODES * 64];
__device__ float g_deg[N_NODES];
__device__ unsigned char g_pmask[N_NODES];
__device__ int g_list[N_NODES];
__device__ int g_cnt;

// ---------------------------------------------------------------------------
// Kernel 1: softmax gate, zero deg, reset counter
// ---------------------------------------------------------------------------
__global__ void pmask_kernel(const float* __restrict__ ops) {
    int n = blockIdx.x * blockDim.x + threadIdx.x;
    if (n == 0) g_cnt = 0;
    if (n >= N_NODES) return;
    float o0 = ops[n * 4 + 0], o1 = ops[n * 4 + 1];
    float o2 = ops[n * 4 + 2], o3 = ops[n * 4 + 3];
    float mx = fmaxf(fmaxf(o0, o1), fmaxf(o2, o3));
    float e0 = expf(o0 - mx), e1 = expf(o1 - mx);
    float e2 = expf(o2 - mx), e3 = expf(o3 - mx);
    float p0 = e0 / (e0 + e1 + e2 + e3);
    g_pmask[n] = (p0 > 0.5f) ? 1 : 0;
    g_deg[n] = 0.f;
}

// ---------------------------------------------------------------------------
// Kernel 2: gated edge scatter with warp-ballot work redistribution.
// Each lane tests one (edge,dir). Active items are shuffled out and processed
// TWO per iteration: lanes 0-15 do item A (chunk=lane), lanes 16-31 item B.
// Full-warp gathers/reds instead of ~3 divergent lanes doing 16 serial ops.
// ---------------------------------------------------------------------------
__global__ void edge_kernel(const int* __restrict__ ei,
                            const float4* __restrict__ feat4,
                            int E) {
    int t = blockIdx.x * blockDim.x + threadIdx.x;
    int lane = threadIdx.x & 31;
    bool active = false;
    int tgt = 0, srcn = 0;
    if (t < 2 * E) {
        int e = t >> 1, dir = t & 1;
        int s = __ldg(&ei[e]);
        int d = __ldg(&ei[E + e]);
        tgt  = dir ? d : s;
        srcn = dir ? s : d;
        active = (g_pmask[tgt] != 0);
    }
    unsigned m = __ballot_sync(0xffffffffu, active);
    float4* nsum4 = reinterpret_cast<float4*>(g_nsum);
    while (m) {
        int b0 = __ffs(m) - 1; m &= m - 1;
        int b1 = -1;
        if (m) { b1 = __ffs(m) - 1; m &= m - 1; }
        int myb = (lane < 16) ? b0 : b1;
        bool go = (myb >= 0);
        int bb = go ? myb : b0;
        int T = __shfl_sync(0xffffffffu, tgt,  bb);
        int S = __shfl_sync(0xffffffffu, srcn, bb);
        if (go) {
            int c = lane & 15;
            float4 v = __ldg(&feat4[(size_t)S * 16 + c]);
            asm volatile("red.global.add.v4.f32 [%0], {%1,%2,%3,%4};" ::
                         "l"(nsum4 + (size_t)T * 16 + c),
                         "f"(v.x), "f"(v.y), "f"(v.z), "f"(v.w) : "memory");
            if (c == 0) atomicAdd(&g_deg[T], 1.f);
        }
    }
}

// ---------------------------------------------------------------------------
// Kernel 3: compact active nodes
// ---------------------------------------------------------------------------
__global__ void compact_kernel() {
    int n = blockIdx.x * blockDim.x + threadIdx.x;
    if (n >= N_NODES) return;
    if (g_pmask[n] && g_deg[n] > 0.f) {
        int p = atomicAdd(&g_cnt, 1);
        g_list[p] = n;
    }
}

// ---------------------------------------------------------------------------
// Kernel 4: MLP over active nodes. 24 warps/block (occ 37.5%), weights in
// SMEM, ping-pong activation buffer (2 KB/warp), float4 activation reads.
// ---------------------------------------------------------------------------
#define WARPS 24
#define THREADS (WARPS * 32)
#define NPW 4

#define OFF_W1   0          // 128*128
#define OFF_B1   16384      // 128
#define OFF_W2   16512      // 128*64
#define OFF_B2   24704      // 64
#define OFF_W3   24768      // 64*67
#define OFF_B3   29056      // 67 (+1 pad)
#define OFF_P1   29124      // 64*32
#define OFF_PB1  31172      // 32
#define OFF_P2   31204      // 32
#define OFF_PB2  31236      // 1 (+3 pad)
#define OFF_SCR  31240      // per-warp: NPW*128 floats
#define SMEM_FLOATS (OFF_SCR + WARPS * NPW * 128)

__global__ void __launch_bounds__(THREADS, 1)
mlp_kernel(const float* __restrict__ nf,
           const float* __restrict__ W1, const float* __restrict__ b1,
           const float* __restrict__ W2, const float* __restrict__ b2,
           const float* __restrict__ W3, const float* __restrict__ b3,
           const float* __restrict__ P1, const float* __restrict__ pb1,
           const float* __restrict__ P2, const float* __restrict__ pb2,
           float* __restrict__ out) {
    extern __shared__ float sm[];
    int tid = threadIdx.x;

    for (int i = tid; i < 16384; i += THREADS) sm[OFF_W1 + i] = W1[i];
    for (int i = tid; i < 128;   i += THREADS) sm[OFF_B1 + i] = b1[i];
    for (int i = tid; i < 8192;  i += THREADS) sm[OFF_W2 + i] = W2[i];
    for (int i = tid; i < 64;    i += THREADS) sm[OFF_B2 + i] = b2[i];
    for (int i = tid; i < 4288;  i += THREADS) sm[OFF_W3 + i] = W3[i];
    for (int i = tid; i < 67;    i += THREADS) sm[OFF_B3 + i] = b3[i];
    for (int i = tid; i < 2048;  i += THREADS) sm[OFF_P1 + i] = P1[i];
    for (int i = tid; i < 32;    i += THREADS) sm[OFF_PB1 + i] = pb1[i];
    for (int i = tid; i < 32;    i += THREADS) sm[OFF_P2 + i] = P2[i];
    if (tid == 0) sm[OFF_PB2] = pb2[0];
    __syncthreads();

    int warpId = tid >> 5;
    int lane   = tid & 31;
    float* buf = sm + OFF_SCR + warpId * (NPW * 128);   // ping-pong [NPW][128]
    float4* buf4 = reinterpret_cast<float4*>(buf);      // [NPW][32]

    const float4* sW1_4 = reinterpret_cast<const float4*>(sm + OFF_W1);
    const float4* sb1_4 = reinterpret_cast<const float4*>(sm + OFF_B1);
    const float2* sW2_2 = reinterpret_cast<const float2*>(sm + OFF_W2);
    const float2* sb2_2 = reinterpret_cast<const float2*>(sm + OFF_B2);

    const int cnt = g_cnt;
    const int totalWarps = gridDim.x * WARPS;

    for (int g = blockIdx.x * WARPS + warpId; g * NPW < cnt; g += totalWarps) {
        int nn[NPW];
        bool valid[NPW];
        #pragma unroll
        for (int q = 0; q < NPW; q++) {
            int li = g * NPW + q;
            valid[q] = li < cnt;
            nn[q] = g_list[valid[q] ? li : g * NPW];
        }

        // ---- ctx = [feat | nmean] into buf ----
        #pragma unroll
        for (int q = 0; q < NPW; q++) {
            int n = nn[q];
            float inv = 1.f / fmaxf(g_deg[n], 1.f);
            buf[q * 128 + lane]      = nf[(size_t)n * 64 + lane];
            buf[q * 128 + 32 + lane] = nf[(size_t)n * 64 + 32 + lane];
            buf[q * 128 + 64 + lane] = g_nsum[(size_t)n * 64 + lane] * inv;
            buf[q * 128 + 96 + lane] = g_nsum[(size_t)n * 64 + 32 + lane] * inv;
        }
        __syncwarp();

        // ---- layer 1: 128 -> 128, relu. lane owns outputs 4*lane..+3 ----
        float4 acc[NPW];
        {
            float4 bb = sb1_4[lane];
            #pragma unroll
            for (int q = 0; q < NPW; q++) acc[q] = bb;
        }
        #pragma unroll 4
        for (int i4 = 0; i4 < 32; i4++) {
            float4 c[NPW];
            #pragma unroll
            for (int q = 0; q < NPW; q++) c[q] = buf4[q * 32 + i4];
            #pragma unroll
            for (int k = 0; k < 4; k++) {
                float4 w = sW1_4[(i4 * 4 + k) * 32 + lane];
                #pragma unroll
                for (int q = 0; q < NPW; q++) {
                    float cv = (k == 0) ? c[q].x : (k == 1) ? c[q].y
                             : (k == 2) ? c[q].z : c[q].w;
                    acc[q].x += w.x * cv; acc[q].y += w.y * cv;
                    acc[q].z += w.z * cv; acc[q].w += w.w * cv;
                }
            }
        }
        __syncwarp();
        #pragma unroll
        for (int q = 0; q < NPW; q++) {
            buf[q * 128 + 4 * lane + 0] = fmaxf(acc[q].x, 0.f);
            buf[q * 128 + 4 * lane + 1] = fmaxf(acc[q].y, 0.f);
            buf[q * 128 + 4 * lane + 2] = fmaxf(acc[q].z, 0.f);
            buf[q * 128 + 4 * lane + 3] = fmaxf(acc[q].w, 0.f);
        }
        __syncwarp();

        // ---- layer 2: 128 -> 64, relu. lane owns outputs 2*lane..+1 ----
        float2 a2[NPW];
        {
            float2 bb = sb2_2[lane];
            #pragma unroll
            for (int q = 0; q < NPW; q++) a2[q] = bb;
        }
        #pragma unroll 4
        for (int i4 = 0; i4 < 32; i4++) {
            float4 c[NPW];
            #pragma unroll
            for (int q = 0; q < NPW; q++) c[q] = buf4[q * 32 + i4];
            #pragma unroll
            for (int k = 0; k < 4; k++) {
                float2 w = sW2_2[(i4 * 4 + k) * 32 + lane];
                #pragma unroll
                for (int q = 0; q < NPW; q++) {
                    float cv = (k == 0) ? c[q].x : (k == 1) ? c[q].y
                             : (k == 2) ? c[q].z : c[q].w;
                    a2[q].x += w.x * cv; a2[q].y += w.y * cv;
                }
            }
        }
        __syncwarp();
        #pragma unroll
        for (int q = 0; q < NPW; q++) {
            buf[q * 128 + 2 * lane + 0] = fmaxf(a2[q].x, 0.f);
            buf[q * 128 + 2 * lane + 1] = fmaxf(a2[q].y, 0.f);
        }
        __syncwarp();

        // ---- layer 3: 64 -> 67. lane owns outputs lane, lane+32, lane+64(<3)
        float ga[NPW], gb2[NPW], gc[NPW];
        {
            float bA = sm[OFF_B3 + lane];
            float bB = sm[OFF_B3 + 32 + lane];
            float bC = (lane < 3) ? sm[OFF_B3 + 64 + lane] : 0.f;
            #pragma unroll
            for (int q = 0; q < NPW; q++) { ga[q] = bA; gb2[q] = bB; gc[q] = bC; }
        }
        #pragma unroll 2
        for (int i4 = 0; i4 < 16; i4++) {
            float4 c[NPW];
            #pragma unroll
            for (int q = 0; q < NPW; q++) c[q] = buf4[q * 32 + i4];
            #pragma unroll
            for (int k = 0; k < 4; k++) {
                int i = i4 * 4 + k;
                float w1 = sm[OFF_W3 + i * 67 + lane];
                float w2 = sm[OFF_W3 + i * 67 + 32 + lane];
                float w3 = (lane < 3) ? sm[OFF_W3 + i * 67 + 64 + lane] : 0.f;
                #pragma unroll
                for (int q = 0; q < NPW; q++) {
                    float cv = (k == 0) ? c[q].x : (k == 1) ? c[q].y
                             : (k == 2) ? c[q].z : c[q].w;
                    ga[q] += cv * w1; gb2[q] += cv * w2; gc[q] += cv * w3;
                }
            }
        }
        __syncwarp();
        #pragma unroll
        for (int q = 0; q < NPW; q++) {
            buf[q * 128 + lane]      = ga[q];
            buf[q * 128 + 32 + lane] = gb2[q];
            if (lane < 3) buf[q * 128 + 64 + lane] = gc[q];
        }
        __syncwarp();

        // ---- head: feats = buf[3..66] -> 32 relu -> 1 sigmoid ----
        float pa[NPW];
        {
            float bb = sm[OFF_PB1 + lane];
            #pragma unroll
            for (int q = 0; q < NPW; q++) pa[q] = bb;
        }
        #pragma unroll 2
        for (int i = 0; i < 64; i++) {
            float w = sm[OFF_P1 + i * 32 + lane];
            #pragma unroll
            for (int q = 0; q < NPW; q++) pa[q] += buf[q * 128 + 3 + i] * w;
        }
        float prob[NPW];
        float w2s = sm[OFF_P2 + lane];
        float pb2v = sm[OFF_PB2];
        #pragma unroll
        for (int q = 0; q < NPW; q++) {
            float v = fmaxf(pa[q], 0.f) * w2s;
            #pragma unroll
            for (int o = 16; o > 0; o >>= 1)
                v += __shfl_xor_sync(0xffffffffu, v, o);
            prob[q] = 1.f / (1.f + expf(-(v + pb2v)));
        }

        // ---- write out ----
        #pragma unroll
        for (int q = 0; q < NPW; q++) {
            if (!valid[q]) continue;
            float* o = out + (size_t)nn[q] * OUTW;
            o[lane]      = buf[q * 128 + lane];
            o[32 + lane] = buf[q * 128 + 32 + lane];
            if (lane < 3) o[64 + lane] = buf[q * 128 + 64 + lane];
            if (lane == 3) o[67] = prob[q];
        }
        __syncwarp();
    }
}

// ---------------------------------------------------------------------------
extern "C" void kernel_launch(void* const* d_in, const int* in_sizes, int n_in,
                              void* d_out, int out_size) {
    const float* nf  = (const float*)d_in[0];
    const float* ops = (const float*)d_in[1];
    const int*   ei  = (const int*)d_in[2];
    const float* W1  = (const float*)d_in[3];
    const float* b1  = (const float*)d_in[4];
    const float* W2  = (const float*)d_in[5];
    const float* b2  = (const float*)d_in[6];
    const float* W3  = (const float*)d_in[7];
    const float* b3  = (const float*)d_in[8];
    const float* P1  = (const float*)d_in[9];
    const float* pb1 = (const float*)d_in[10];
    const float* P2  = (const float*)d_in[11];
    const float* pb2 = (const float*)d_in[12];
    float* out = (float*)d_out;

    int E = in_sizes[2] / 2;

    void* p_nsum = nullptr;
    cudaGetSymbolAddress(&p_nsum, g_nsum);
    cudaMemsetAsync(d_out, 0, (size_t)out_size * sizeof(float));
    cudaMemsetAsync(p_nsum, 0, sizeof(float) * (size_t)N_NODES * 64);

    pmask_kernel<<<(N_NODES + 255) / 256, 256>>>(ops);

    int tthreads = 2 * E;
    edge_kernel<<<(tthreads + 255) / 256, 256>>>(ei, (const float4*)nf, E);

    compact_kernel<<<(N_NODES + 255) / 256, 256>>>();

    static_assert(SMEM_FLOATS * 4 < 227 * 1024, "smem");
    cudaFuncSetAttribute(mlp_kernel,
                         cudaFuncAttributeMaxDynamicSharedMemorySize,
                         SMEM_FLOATS * 4);
    mlp_kernel<<<152, THREADS, SMEM_FLOATS * 4>>>(
        nf, W1, b1, W2, b2, W3, b3, P1, pb1, P2, pb2, out);
}

// round 4
// speedup vs baseline: 6.2889x; 1.7227x over previous
#include <cuda_runtime.h>
#include <cstdint>

#define N_NODES 100000
#define OUTW 68
typedef unsigned long long u64;

__device__ float g_nsum[(size_t)N_NODES * 64];
__device__ float g_deg[N_NODES];
__device__ unsigned g_pmaskbits[3136];
__device__ int g_list[N_NODES];
__device__ int g_cnt;

// ---- packed-f32 helpers (FFMA2 path; sm_103a) ------------------------------
__device__ __forceinline__ u64 pack2s(float v) {           // splat (v,v)
    u64 r; asm("mov.b64 %0, {%1, %1};" : "=l"(r) : "f"(v)); return r;
}
__device__ __forceinline__ u64 pack2(float a, float b) {   // (a,b)
    u64 r; asm("mov.b64 %0, {%1, %2};" : "=l"(r) : "f"(a), "f"(b)); return r;
}
__device__ __forceinline__ void ffma2(u64& d, u64 a, u64 b) {
    asm("fma.rn.f32x2 %0, %1, %2, %3;" : "=l"(d) : "l"(a), "l"(b), "l"(d));
}
__device__ __forceinline__ void unpack2(u64 v, float& a, float& b) {
    asm("mov.b64 {%0, %1}, %2;" : "=f"(a), "=f"(b) : "l"(v));
}

// ---------------------------------------------------------------------------
// Kernel 1: softmax gate -> bit mask (warp ballot), zero deg, zero nsum rows
// of masked nodes (replaces the 25.6MB memset), reset counter.
// ---------------------------------------------------------------------------
__global__ void pmask_kernel(const float* __restrict__ ops) {
    int n = blockIdx.x * blockDim.x + threadIdx.x;
    if (n == 0) g_cnt = 0;
    bool msk = false;
    if (n < N_NODES) {
        float o0 = ops[n * 4 + 0], o1 = ops[n * 4 + 1];
        float o2 = ops[n * 4 + 2], o3 = ops[n * 4 + 3];
        float mx = fmaxf(fmaxf(o0, o1), fmaxf(o2, o3));
        float e0 = expf(o0 - mx), e1 = expf(o1 - mx);
        float e2 = expf(o2 - mx), e3 = expf(o3 - mx);
        float p0 = e0 / (e0 + e1 + e2 + e3);
        msk = (p0 > 0.5f);
        g_deg[n] = 0.f;
    }
    unsigned bits = __ballot_sync(0xffffffffu, msk);
    if ((threadIdx.x & 31) == 0 && (n & ~31) < N_NODES)
        g_pmaskbits[n >> 5] = bits;
    if (msk) {
        float4 z = make_float4(0.f, 0.f, 0.f, 0.f);
        float4* row = reinterpret_cast<float4*>(g_nsum) + (size_t)n * 16;
        #pragma unroll
        for (int c = 0; c < 16; c++) row[c] = z;
    }
}

// ---------------------------------------------------------------------------
// Kernel 2: gated edge scatter, ballot work redistribution (2 items/iter,
// 16 lanes each). Mask test from L1-resident 12.5KB bit array.
// ---------------------------------------------------------------------------
__global__ void edge_kernel(const int* __restrict__ ei,
                            const float4* __restrict__ feat4,
                            int E) {
    int t = blockIdx.x * blockDim.x + threadIdx.x;
    int lane = threadIdx.x & 31;
    bool active = false;
    int tgt = 0, srcn = 0;
    if (t < 2 * E) {
        int e = t >> 1, dir = t & 1;
        int s = __ldg(&ei[e]);
        int d = __ldg(&ei[E + e]);
        tgt  = dir ? d : s;
        srcn = dir ? s : d;
        active = (g_pmaskbits[tgt >> 5] >> (tgt & 31)) & 1;
    }
    unsigned m = __ballot_sync(0xffffffffu, active);
    float4* nsum4 = reinterpret_cast<float4*>(g_nsum);
    while (m) {
        int b0 = __ffs(m) - 1; m &= m - 1;
        int b1 = -1;
        if (m) { b1 = __ffs(m) - 1; m &= m - 1; }
        int myb = (lane < 16) ? b0 : b1;
        bool go = (myb >= 0);
        int bb = go ? myb : b0;
        int T = __shfl_sync(0xffffffffu, tgt,  bb);
        int S = __shfl_sync(0xffffffffu, srcn, bb);
        if (go) {
            int c = lane & 15;
            float4 v = __ldg(&feat4[(size_t)S * 16 + c]);
            asm volatile("red.global.add.v4.f32 [%0], {%1,%2,%3,%4};" ::
                         "l"(nsum4 + (size_t)T * 16 + c),
                         "f"(v.x), "f"(v.y), "f"(v.z), "f"(v.w) : "memory");
            if (c == 0) atomicAdd(&g_deg[T], 1.f);
        }
    }
}

// ---------------------------------------------------------------------------
// Kernel 3: compact active nodes (warp-aggregated atomic)
// ---------------------------------------------------------------------------
__global__ void compact_kernel() {
    int n = blockIdx.x * blockDim.x + threadIdx.x;
    int lane = threadIdx.x & 31;
    bool act = false;
    if (n < N_NODES)
        act = ((g_pmaskbits[n >> 5] >> (n & 31)) & 1) && (g_deg[n] > 0.f);
    unsigned m = __ballot_sync(0xffffffffu, act);
    int base = 0;
    if (lane == 0 && m) base = atomicAdd(&g_cnt, __popc(m));
    base = __shfl_sync(0xffffffffu, base, 0);
    if (act) g_list[base + __popc(m & ((1u << lane) - 1))] = n;
}

// ---------------------------------------------------------------------------
// Kernel 4: MLP with FFMA2 packed-f32 math in layers 1-2.
// ---------------------------------------------------------------------------
#define WARPS 24
#define THREADS (WARPS * 32)
#define NPW 4

#define OFF_W1   0          // 128*128
#define OFF_B1   16384      // 128
#define OFF_W2   16512      // 128*64
#define OFF_B2   24704      // 64
#define OFF_W3   24768      // 64*67
#define OFF_B3   29056      // 67 (+1 pad)
#define OFF_P1   29124      // 64*32
#define OFF_PB1  31172      // 32
#define OFF_P2   31204      // 32
#define OFF_PB2  31236      // 1 (+3 pad)
#define OFF_SCR  31240      // per-warp: NPW*128 floats
#define SMEM_FLOATS (OFF_SCR + WARPS * NPW * 128)

__global__ void __launch_bounds__(THREADS, 1)
mlp_kernel(const float* __restrict__ nf,
           const float* __restrict__ W1, const float* __restrict__ b1,
           const float* __restrict__ W2, const float* __restrict__ b2,
           const float* __restrict__ W3, const float* __restrict__ b3,
           const float* __restrict__ P1, const float* __restrict__ pb1,
           const float* __restrict__ P2, const float* __restrict__ pb2,
           float* __restrict__ out) {
    extern __shared__ float sm[];
    int tid = threadIdx.x;

    for (int i = tid; i < 16384; i += THREADS) sm[OFF_W1 + i] = W1[i];
    for (int i = tid; i < 128;   i += THREADS) sm[OFF_B1 + i] = b1[i];
    for (int i = tid; i < 8192;  i += THREADS) sm[OFF_W2 + i] = W2[i];
    for (int i = tid; i < 64;    i += THREADS) sm[OFF_B2 + i] = b2[i];
    for (int i = tid; i < 4288;  i += THREADS) sm[OFF_W3 + i] = W3[i];
    for (int i = tid; i < 67;    i += THREADS) sm[OFF_B3 + i] = b3[i];
    for (int i = tid; i < 2048;  i += THREADS) sm[OFF_P1 + i] = P1[i];
    for (int i = tid; i < 32;    i += THREADS) sm[OFF_PB1 + i] = pb1[i];
    for (int i = tid; i < 32;    i += THREADS) sm[OFF_P2 + i] = P2[i];
    if (tid == 0) sm[OFF_PB2] = pb2[0];
    __syncthreads();

    int warpId = tid >> 5;
    int lane   = tid & 31;
    float* buf = sm + OFF_SCR + warpId * (NPW * 128);   // ping-pong [NPW][128]
    float4* buf4 = reinterpret_cast<float4*>(buf);

    const ulonglong2* sW1u = reinterpret_cast<const ulonglong2*>(sm + OFF_W1);
    const float4*     sb1_4 = reinterpret_cast<const float4*>(sm + OFF_B1);
    const u64*        sW2u = reinterpret_cast<const u64*>(sm + OFF_W2);
    const float2*     sb2_2 = reinterpret_cast<const float2*>(sm + OFF_B2);

    const int cnt = g_cnt;
    const int totalWarps = gridDim.x * WARPS;

    for (int g = blockIdx.x * WARPS + warpId; g * NPW < cnt; g += totalWarps) {
        int nn[NPW];
        bool valid[NPW];
        #pragma unroll
        for (int q = 0; q < NPW; q++) {
            int li = g * NPW + q;
            valid[q] = li < cnt;
            nn[q] = g_list[valid[q] ? li : g * NPW];
        }

        // ---- ctx = [feat | nmean] ----
        #pragma unroll
        for (int q = 0; q < NPW; q++) {
            int n = nn[q];
            float inv = 1.f / fmaxf(g_deg[n], 1.f);
            buf[q * 128 + lane]      = nf[(size_t)n * 64 + lane];
            buf[q * 128 + 32 + lane] = nf[(size_t)n * 64 + 32 + lane];
            buf[q * 128 + 64 + lane] = g_nsum[(size_t)n * 64 + lane] * inv;
            buf[q * 128 + 96 + lane] = g_nsum[(size_t)n * 64 + 32 + lane] * inv;
        }
        __syncwarp();

        // ---- layer 1: 128 -> 128 relu, FFMA2. lane owns outs 4*lane..+3 ----
        u64 acc01[NPW], acc23[NPW];
        {
            float4 bb = sb1_4[lane];
            u64 i01 = pack2(bb.x, bb.y), i23 = pack2(bb.z, bb.w);
            #pragma unroll
            for (int q = 0; q < NPW; q++) { acc01[q] = i01; acc23[q] = i23; }
        }
        #pragma unroll 4
        for (int i4 = 0; i4 < 32; i4++) {
            float4 c[NPW];
            #pragma unroll
            for (int q = 0; q < NPW; q++) c[q] = buf4[q * 32 + i4];
            #pragma unroll
            for (int k = 0; k < 4; k++) {
                ulonglong2 w = sW1u[(i4 * 4 + k) * 32 + lane];
                #pragma unroll
                for (int q = 0; q < NPW; q++) {
                    float cv = (k == 0) ? c[q].x : (k == 1) ? c[q].y
                             : (k == 2) ? c[q].z : c[q].w;
                    u64 cv2 = pack2s(cv);
                    ffma2(acc01[q], w.x, cv2);
                    ffma2(acc23[q], w.y, cv2);
                }
            }
        }
        __syncwarp();
        #pragma unroll
        for (int q = 0; q < NPW; q++) {
            float a0, a1, a2v, a3;
            unpack2(acc01[q], a0, a1);
            unpack2(acc23[q], a2v, a3);
            buf4[q * 32 + lane] = make_float4(fmaxf(a0, 0.f), fmaxf(a1, 0.f),
                                              fmaxf(a2v, 0.f), fmaxf(a3, 0.f));
        }
        __syncwarp();

        // ---- layer 2: 128 -> 64 relu, FFMA2. lane owns outs 2*lane..+1 ----
        u64 acc2[NPW];
        {
            float2 bb = sb2_2[lane];
            u64 ii = pack2(bb.x, bb.y);
            #pragma unroll
            for (int q = 0; q < NPW; q++) acc2[q] = ii;
        }
        #pragma unroll 4
        for (int i4 = 0; i4 < 32; i4++) {
            float4 c[NPW];
            #pragma unroll
            for (int q = 0; q < NPW; q++) c[q] = buf4[q * 32 + i4];
            #pragma unroll
            for (int k = 0; k < 4; k++) {
                u64 w = sW2u[(i4 * 4 + k) * 32 + lane];
                #pragma unroll
                for (int q = 0; q < NPW; q++) {
                    float cv = (k == 0) ? c[q].x : (k == 1) ? c[q].y
                             : (k == 2) ? c[q].z : c[q].w;
                    ffma2(acc2[q], w, pack2s(cv));
                }
            }
        }
        __syncwarp();
        #pragma unroll
        for (int q = 0; q < NPW; q++) {
            float a0, a1;
            unpack2(acc2[q], a0, a1);
            buf[q * 128 + 2 * lane + 0] = fmaxf(a0, 0.f);
            buf[q * 128 + 2 * lane + 1] = fmaxf(a1, 0.f);
        }
        __syncwarp();

        // ---- layer 3: 64 -> 67 ----
        float ga[NPW], gb2[NPW], gc[NPW];
        {
            float bA = sm[OFF_B3 + lane];
            float bB = sm[OFF_B3 + 32 + lane];
            float bC = (lane < 3) ? sm[OFF_B3 + 64 + lane] : 0.f;
            #pragma unroll
            for (int q = 0; q < NPW; q++) { ga[q] = bA; gb2[q] = bB; gc[q] = bC; }
        }
        #pragma unroll 2
        for (int i4 = 0; i4 < 16; i4++) {
            float4 c[NPW];
            #pragma unroll
            for (int q = 0; q < NPW; q++) c[q] = buf4[q * 32 + i4];
            #pragma unroll
            for (int k = 0; k < 4; k++) {
                int i = i4 * 4 + k;
                float w1 = sm[OFF_W3 + i * 67 + lane];
                float w2 = sm[OFF_W3 + i * 67 + 32 + lane];
                float w3 = (lane < 3) ? sm[OFF_W3 + i * 67 + 64 + lane] : 0.f;
                #pragma unroll
                for (int q = 0; q < NPW; q++) {
                    float cv = (k == 0) ? c[q].x : (k == 1) ? c[q].y
                             : (k == 2) ? c[q].z : c[q].w;
                    ga[q] += cv * w1; gb2[q] += cv * w2; gc[q] += cv * w3;
                }
            }
        }
        __syncwarp();
        #pragma unroll
        for (int q = 0; q < NPW; q++) {
            buf[q * 128 + lane]      = ga[q];
            buf[q * 128 + 32 + lane] = gb2[q];
            if (lane < 3) buf[q * 128 + 64 + lane] = gc[q];
        }
        __syncwarp();

        // ---- head: feats = buf[3..66] -> 32 relu -> 1 sigmoid ----
        float pa[NPW];
        {
            float bb = sm[OFF_PB1 + lane];
            #pragma unroll
            for (int q = 0; q < NPW; q++) pa[q] = bb;
        }
        #pragma unroll 2
        for (int i = 0; i < 64; i++) {
            float w = sm[OFF_P1 + i * 32 + lane];
            #pragma unroll
            for (int q = 0; q < NPW; q++) pa[q] += buf[q * 128 + 3 + i] * w;
        }
        float prob[NPW];
        float w2s = sm[OFF_P2 + lane];
        float pb2v = sm[OFF_PB2];
        #pragma unroll
        for (int q = 0; q < NPW; q++) {
            float v = fmaxf(pa[q], 0.f) * w2s;
            #pragma unroll
            for (int o = 16; o > 0; o >>= 1)
                v += __shfl_xor_sync(0xffffffffu, v, o);
            prob[q] = 1.f / (1.f + expf(-(v + pb2v)));
        }

        // ---- write out ----
        #pragma unroll
        for (int q = 0; q < NPW; q++) {
            if (!valid[q]) continue;
            float* o = out + (size_t)nn[q] * OUTW;
            o[lane]      = buf[q * 128 + lane];
            o[32 + lane] = buf[q * 128 + 32 + lane];
            if (lane < 3) o[64 + lane] = buf[q * 128 + 64 + lane];
            if (lane == 3) o[67] = prob[q];
        }
        __syncwarp();
    }
}

// ---------------------------------------------------------------------------
extern "C" void kernel_launch(void* const* d_in, const int* in_sizes, int n_in,
                              void* d_out, int out_size) {
    const float* nf  = (const float*)d_in[0];
    const float* ops = (const float*)d_in[1];
    const int*   ei  = (const int*)d_in[2];
    const float* W1  = (const float*)d_in[3];
    const float* b1  = (const float*)d_in[4];
    const float* W2  = (const float*)d_in[5];
    const float* b2  = (const float*)d_in[6];
    const float* W3  = (const float*)d_in[7];
    const float* b3  = (const float*)d_in[8];
    const float* P1  = (const float*)d_in[9];
    const float* pb1 = (const float*)d_in[10];
    const float* P2  = (const float*)d_in[11];
    const float* pb2 = (const float*)d_in[12];
    float* out = (float*)d_out;

    int E = in_sizes[2] / 2;

    cudaMemsetAsync(d_out, 0, (size_t)out_size * sizeof(float));

    pmask_kernel<<<(N_NODES + 255) / 256, 256>>>(ops);

    int tthreads = 2 * E;
    edge_kernel<<<(tthreads + 255) / 256, 256>>>(ei, (const float4*)nf, E);

    compact_kernel<<<(N_NODES + 255) / 256, 256>>>();

    static_assert(SMEM_FLOATS * 4 < 227 * 1024, "smem");
    cudaFuncSetAttribute(mlp_kernel,
                         cudaFuncAttributeMaxDynamicSharedMemorySize,
                         SMEM_FLOATS * 4);
    mlp_kernel<<<152, THREADS, SMEM_FLOATS * 4>>>(
        nf, W1, b1, W2, b2, W3, b3, P1, pb1, P2, pb2, out);
}